// round 2
// baseline (speedup 1.0000x reference)
#include <cuda_runtime.h>
#include <cstdint>

// MessagePassing: out[t] += r[s]*e ; out[s] += r[t]*e  per edge (s,t)
// Inputs (metadata order): d_in[0]=r [50000,128] f32, d_in[1]=e [500000,128] f32,
//                          d_in[2]=a [500000,2] int32 (JAX x64 disabled downcasts int64).
// d_out: [50000,128] f32.

#define D_FEAT 128
#define WARPS_PER_BLOCK 8

__device__ __forceinline__ void red_add_v4(float* addr, float4 v) {
    asm volatile("red.global.add.v4.f32 [%0], {%1,%2,%3,%4};"
                 :: "l"(addr), "f"(v.x), "f"(v.y), "f"(v.z), "f"(v.w)
                 : "memory");
}

__global__ __launch_bounds__(WARPS_PER_BLOCK * 32)
void mp_edge_kernel(const float* __restrict__ r,
                    const float* __restrict__ e,
                    const int* __restrict__ a,
                    float* __restrict__ out,
                    int n_edges) {
    int edge = blockIdx.x * WARPS_PER_BLOCK + (threadIdx.x >> 5);
    if (edge >= n_edges) return;
    int lane = threadIdx.x & 31;

    // edge endpoints (int32 pair, 8B); one vectorized load, broadcast within warp via L1
    int2 st = __ldg(reinterpret_cast<const int2*>(a) + edge);
    long long s = st.x;
    long long t = st.y;

    const float4* e4  = reinterpret_cast<const float4*>(e + (long long)edge * D_FEAT);
    const float4* rs4 = reinterpret_cast<const float4*>(r + s * D_FEAT);
    const float4* rt4 = reinterpret_cast<const float4*>(r + t * D_FEAT);

    // e is streamed once: use .cs to avoid evicting L2-resident r/out
    float4 ev  = __ldcs(e4 + lane);
    float4 rsv = __ldg(rs4 + lane);
    float4 rtv = __ldg(rt4 + lane);

    float4 m_to_t = make_float4(rsv.x * ev.x, rsv.y * ev.y, rsv.z * ev.z, rsv.w * ev.w);
    float4 m_to_s = make_float4(rtv.x * ev.x, rtv.y * ev.y, rtv.z * ev.z, rtv.w * ev.w);

    red_add_v4(reinterpret_cast<float*>(reinterpret_cast<float4*>(out + t * D_FEAT) + lane), m_to_t);
    red_add_v4(reinterpret_cast<float*>(reinterpret_cast<float4*>(out + s * D_FEAT) + lane), m_to_s);
}

extern "C" void kernel_launch(void* const* d_in, const int* in_sizes, int n_in,
                              void* d_out, int out_size) {
    const float* r = (const float*)d_in[0];
    const float* e = (const float*)d_in[1];
    const int*   a = (const int*)d_in[2];
    float*     out = (float*)d_out;

    int n_edges = in_sizes[1] / D_FEAT;  // 500000

    // d_out is poisoned (0xAA) before timing; zero it (graph-capturable memset node)
    cudaMemsetAsync(d_out, 0, (size_t)out_size * sizeof(float), 0);

    int blocks = (n_edges + WARPS_PER_BLOCK - 1) / WARPS_PER_BLOCK;
    mp_edge_kernel<<<blocks, WARPS_PER_BLOCK * 32>>>(r, e, a, out, n_edges);
}

// round 3
// speedup vs baseline: 1.0615x; 1.0615x over previous
#include <cuda_runtime.h>
#include <cstdint>

// MessagePassing: out[t] += r[s]*e ; out[s] += r[t]*e  per edge (s,t)
// Inputs: d_in[0]=r [50000,128] f32, d_in[1]=e [500000,128] f32,
//         d_in[2]=a [500000,2] int32. d_out: [50000,128] f32.
//
// Warp processes TWO edges: one int4 grabs both edges' (s,t) pairs, all six
// float4 loads are hoisted (MLP ~7/warp), then four vector REDs are issued.

#define D_FEAT 128
#define WARPS_PER_BLOCK 8

__device__ __forceinline__ void red_add_v4(float* addr, float4 v) {
    asm volatile("red.global.add.v4.f32 [%0], {%1,%2,%3,%4};"
                 :: "l"(addr), "f"(v.x), "f"(v.y), "f"(v.z), "f"(v.w)
                 : "memory");
}

__device__ __forceinline__ float4 mul4(float4 a, float4 b) {
    return make_float4(a.x * b.x, a.y * b.y, a.z * b.z, a.w * b.w);
}

__global__ __launch_bounds__(WARPS_PER_BLOCK * 32)
void mp_edge2_kernel(const float* __restrict__ r,
                     const float* __restrict__ e,
                     const int4* __restrict__ a2,   // a viewed as [E/2] x (s0,t0,s1,t1)
                     float* __restrict__ out,
                     int n_pairs) {
    int pair = blockIdx.x * WARPS_PER_BLOCK + (threadIdx.x >> 5);
    if (pair >= n_pairs) return;
    int lane = threadIdx.x & 31;

    // both edges' endpoints in one 16B load (warp-broadcast in L1)
    int4 st = __ldg(a2 + pair);
    long long s0 = st.x, t0 = st.y, s1 = st.z, t1 = st.w;
    long long e0 = 2LL * pair, e1 = e0 + 1;

    const float4* ep0 = reinterpret_cast<const float4*>(e + e0 * D_FEAT) + lane;
    const float4* ep1 = reinterpret_cast<const float4*>(e + e1 * D_FEAT) + lane;
    const float4* rs0 = reinterpret_cast<const float4*>(r + s0 * D_FEAT) + lane;
    const float4* rt0 = reinterpret_cast<const float4*>(r + t0 * D_FEAT) + lane;
    const float4* rs1 = reinterpret_cast<const float4*>(r + s1 * D_FEAT) + lane;
    const float4* rt1 = reinterpret_cast<const float4*>(r + t1 * D_FEAT) + lane;

    // hoist all loads: 6 independent 16B loads in flight per lane
    float4 ev0  = __ldcs(ep0);          // e streamed once — don't pollute L2
    float4 ev1  = __ldcs(ep1);
    float4 rsv0 = __ldg(rs0);
    float4 rtv0 = __ldg(rt0);
    float4 rsv1 = __ldg(rs1);
    float4 rtv1 = __ldg(rt1);

    float4* o_t0 = reinterpret_cast<float4*>(out + t0 * D_FEAT) + lane;
    float4* o_s0 = reinterpret_cast<float4*>(out + s0 * D_FEAT) + lane;
    float4* o_t1 = reinterpret_cast<float4*>(out + t1 * D_FEAT) + lane;
    float4* o_s1 = reinterpret_cast<float4*>(out + s1 * D_FEAT) + lane;

    red_add_v4(reinterpret_cast<float*>(o_t0), mul4(rsv0, ev0));
    red_add_v4(reinterpret_cast<float*>(o_s0), mul4(rtv0, ev0));
    red_add_v4(reinterpret_cast<float*>(o_t1), mul4(rsv1, ev1));
    red_add_v4(reinterpret_cast<float*>(o_s1), mul4(rtv1, ev1));
}

extern "C" void kernel_launch(void* const* d_in, const int* in_sizes, int n_in,
                              void* d_out, int out_size) {
    const float* r = (const float*)d_in[0];
    const float* e = (const float*)d_in[1];
    const int4*  a2 = (const int4*)d_in[2];
    float*     out = (float*)d_out;

    int n_edges = in_sizes[1] / D_FEAT;   // 500000
    int n_pairs = n_edges >> 1;           // 250000 (E is even)

    cudaMemsetAsync(d_out, 0, (size_t)out_size * sizeof(float), 0);

    int blocks = (n_pairs + WARPS_PER_BLOCK - 1) / WARPS_PER_BLOCK;
    mp_edge2_kernel<<<blocks, WARPS_PER_BLOCK * 32>>>(r, e, a2, out, n_pairs);
}